// round 16
// baseline (speedup 1.0000x reference)
#include <cuda_runtime.h>
#include <cuda_bf16.h>
#include <cuda_fp16.h>
#include <math.h>
#include <stdint.h>

namespace {
constexpr int Bc  = 2;
constexpr int Sc  = 2048;
constexpr int Hc  = 4096;
constexpr int NHc = 32;
constexpr int HDc = 128;
constexpr int Ic  = 11008;
constexpr int Tc  = Bc * Sc;
constexpr int HALFc = HDc / 2;
constexpr float EPSc = 1e-6f;
constexpr float SCALEc = 0.08838834764831843f;
}

// ---------------- device scratch ----------------
__device__ float g_res1[(size_t)Tc * Hc];
__device__ float g_qkv [(size_t)Tc * 3 * Hc];

__device__ __nv_bfloat16 g_q_hi[(size_t)Tc * Hc], g_q_lo[(size_t)Tc * Hc];
__device__ __nv_bfloat16 g_k_hi[(size_t)Tc * Hc], g_k_lo[(size_t)Tc * Hc];

__device__ __half g_n_h1 [(size_t)Tc * Hc], g_n_h2 [(size_t)Tc * Hc];
__device__ __half g_wqkv_h[(size_t)3 * Hc * Hc];
__device__ __half g_vt_h [(size_t)Tc * Hc];
__device__ __half g_at_h [(size_t)Tc * Hc];
__device__ __half g_n2_h [(size_t)Tc * Hc];
__device__ __half g_ac_h [(size_t)Tc * Ic];
__device__ __half g_wo_h [(size_t)Hc * Hc];
__device__ __half g_wgu_h[(size_t)2 * Ic * Hc];
__device__ __half g_wdn_h[(size_t)Hc * Ic];

// ---------------- helpers ----------------
__device__ __forceinline__ uint32_t smem_u32(const void* p) {
    return (uint32_t)__cvta_generic_to_shared(p);
}
__device__ __forceinline__ void ldsm_x4(uint32_t (&r)[4], uint32_t addr) {
    asm volatile("ldmatrix.sync.aligned.m8n8.x4.shared.b16 {%0,%1,%2,%3}, [%4];"
                 : "=r"(r[0]), "=r"(r[1]), "=r"(r[2]), "=r"(r[3]) : "r"(addr));
}
__device__ __forceinline__ void mma_bf16(float (&d)[4], const uint32_t (&a)[4],
                                         uint32_t b0, uint32_t b1) {
    asm volatile("mma.sync.aligned.m16n8k16.row.col.f32.bf16.bf16.f32 "
        "{%0,%1,%2,%3}, {%4,%5,%6,%7}, {%8,%9}, {%0,%1,%2,%3};"
        : "+f"(d[0]), "+f"(d[1]), "+f"(d[2]), "+f"(d[3])
        : "r"(a[0]), "r"(a[1]), "r"(a[2]), "r"(a[3]), "r"(b0), "r"(b1));
}
__device__ __forceinline__ void mma_f16(float (&d)[4], const uint32_t (&a)[4],
                                        uint32_t b0, uint32_t b1) {
    asm volatile("mma.sync.aligned.m16n8k16.row.col.f32.f16.f16.f32 "
        "{%0,%1,%2,%3}, {%4,%5,%6,%7}, {%8,%9}, {%0,%1,%2,%3};"
        : "+f"(d[0]), "+f"(d[1]), "+f"(d[2]), "+f"(d[3])
        : "r"(a[0]), "r"(a[1]), "r"(a[2]), "r"(a[3]), "r"(b0), "r"(b1));
}
__device__ __forceinline__ void cp_async16(uint32_t dst, const void* src) {
    asm volatile("cp.async.cg.shared.global [%0], [%1], 16;" :: "r"(dst), "l"(src));
}
#define CP_COMMIT() asm volatile("cp.async.commit_group;" ::: "memory")
#define CP_WAIT(n)  asm volatile("cp.async.wait_group %0;" :: "n"(n) : "memory")
__device__ __forceinline__ void split2(float v, __nv_bfloat16& h, __nv_bfloat16& l) {
    h = __float2bfloat16(v);
    l = __float2bfloat16(v - __bfloat162float(h));
}
__device__ __forceinline__ void split2h(float v, __half& h, __half& l) {
    h = __float2half_rn(v);
    l = __float2half_rn(v - __half2float(h));
}

// ---------------- block reductions (256 thr) ----------------
__device__ __forceinline__ float block_reduce_sum_256(float v) {
    #pragma unroll
    for (int o = 16; o > 0; o >>= 1) v += __shfl_down_sync(0xffffffffu, v, o);
    __shared__ float red[8];
    int w = threadIdx.x >> 5, l = threadIdx.x & 31;
    if (l == 0) red[w] = v;
    __syncthreads();
    if (w == 0) {
        float x = (l < 8) ? red[l] : 0.f;
        #pragma unroll
        for (int o = 4; o > 0; o >>= 1) x += __shfl_down_sync(0xffu, x, o);
        if (l == 0) red[0] = x;
    }
    __syncthreads();
    float r = red[0];
    __syncthreads();
    return r;
}

// ------- add + RMSNorm -> fp16 hi/lo duo OR fp16 single plane -------
__global__ __launch_bounds__(256) void add_rmsnorm_kernel(
    const float* __restrict__ a, const float* __restrict__ b,
    const float* __restrict__ w, float* __restrict__ sum_out,
    __half* __restrict__ ohi, __half* __restrict__ olo,
    __half* __restrict__ osingle)
{
    int row = blockIdx.x;
    const float4* a4 = (const float4*)(a + (size_t)row * Hc);
    const float4* b4 = b ? (const float4*)(b + (size_t)row * Hc) : nullptr;
    const float4* w4 = (const float4*)w;
    float4* s4 = sum_out ? (float4*)(sum_out + (size_t)row * Hc) : nullptr;

    float4 v[4];
    float ss = 0.f;
    #pragma unroll
    for (int it = 0; it < 4; it++) {
        int idx = threadIdx.x + it * 256;
        float4 va = a4[idx];
        if (b4) { float4 vb = b4[idx]; va.x += vb.x; va.y += vb.y; va.z += vb.z; va.w += vb.w; }
        v[it] = va;
        ss += va.x * va.x + va.y * va.y + va.z * va.z + va.w * va.w;
    }
    float tot = block_reduce_sum_256(ss);
    float scale = rsqrtf(tot / (float)Hc + EPSc);
    #pragma unroll
    for (int it = 0; it < 4; it++) {
        int idx = threadIdx.x + it * 256;
        if (s4) s4[idx] = v[it];
        float4 vw = w4[idx];
        float y0 = v[it].x * scale * vw.x, y1 = v[it].y * scale * vw.y;
        float y2 = v[it].z * scale * vw.z, y3 = v[it].w * scale * vw.w;
        if (osingle) {
            __half2* o2 = (__half2*)(osingle + (size_t)row * Hc);
            o2[idx*2]   = __half2(__float2half_rn(y0), __float2half_rn(y1));
            o2[idx*2+1] = __half2(__float2half_rn(y2), __float2half_rn(y3));
        } else {
            __half2* oh2 = (__half2*)(ohi + (size_t)row * Hc);
            __half2* ol2 = (__half2*)(olo + (size_t)row * Hc);
            __half h0,l0,h1,l1,h2,l2,h3,l3;
            split2h(y0,h0,l0); split2h(y1,h1,l1); split2h(y2,h2,l2); split2h(y3,h3,l3);
            oh2[idx*2]   = __half2(h0,h1);
            oh2[idx*2+1] = __half2(h2,h3);
            ol2[idx*2]   = __half2(l0,l1);
            ol2[idx*2+1] = __half2(l2,l3);
        }
    }
}

// ------- RoPE: fp32 qkv -> Q/K bf16 hi/lo (SCALE folded into Q) -------
__global__ __launch_bounds__(256) void rope_kernel(
    const float* __restrict__ qkv, const float* __restrict__ cosp,
    const float* __restrict__ sinp,
    __nv_bfloat16* __restrict__ qhi, __nv_bfloat16* __restrict__ qlo,
    __nv_bfloat16* __restrict__ khi, __nv_bfloat16* __restrict__ klo)
{
    int idx = blockIdx.x * 256 + threadIdx.x;
    int d = idx & (HALFc - 1);
    int h = (idx >> 6) & (NHc - 1);
    int m = (idx >> 11) & 1;
    int t = idx >> 12;
    const float* p = qkv + (size_t)t * (3 * Hc) + m * Hc + h * HDc + d;
    float x1 = p[0], x2 = p[HALFc];
    float c = cosp[(size_t)t * HALFc + d];
    float s = sinp[(size_t)t * HALFc + d];
    float sc = m ? 1.f : SCALEc;
    float y1 = (x1 * c - x2 * s) * sc;
    float y2 = (x1 * s + x2 * c) * sc;
    __nv_bfloat16* dh = (m ? khi : qhi) + (size_t)t * Hc + h * HDc + d;
    __nv_bfloat16* dl = (m ? klo : qlo) + (size_t)t * Hc + h * HDc + d;
    __nv_bfloat16 h1, l1, h2, l2;
    split2(y1, h1, l1); split2(y2, h2, l2);
    dh[0] = h1; dh[HALFc] = h2;
    dl[0] = l1; dl[HALFc] = l2;
}

// ------- transpose fp32 [Y,X] -> fp16 [X,Y]; batched; optional interleave -------
__global__ __launch_bounds__(256) void transpose_h16_kernel(
    const float* __restrict__ in, long long inSb, long long inSh, int in_ld,
    __half* __restrict__ outp, long long outSz, int K, int interHalf)
{
    __shared__ float tile[32][33];
    int z = blockIdx.z, zb = z / NHc, zh = z % NHc;
    const float* inp = in + zb * inSb + zh * inSh;
    __half* op = outp + (long long)z * outSz;
    int tx = threadIdx.x & 31, ty = threadIdx.x >> 5;
    int gx = blockIdx.x * 32 + tx;
    #pragma unroll
    for (int i = 0; i < 4; i++) {
        int gy = blockIdx.y * 32 + ty + i * 8;
        tile[ty + i * 8][tx] = inp[(size_t)gy * in_ld + gx];
    }
    __syncthreads();
    int ox = blockIdx.y * 32 + tx;
    #pragma unroll
    for (int i = 0; i < 4; i++) {
        int oy = blockIdx.x * 32 + ty + i * 8;
        int oyr = interHalf ? ((oy < interHalf) ? 2 * oy : 2 * (oy - interHalf) + 1) : oy;
        op[(size_t)oyr * K + ox] = __float2half_rn(tile[tx][ty + i * 8]);
    }
}

// ==================================================================
// Fused flash attention. QK = bf16 3-pass, online softmax fp32,
// PV = fp16 2-pass (p hi/lo). 8 warps x 16 rows.
// ==================================================================
namespace fa {
constexpr int SROW = 136;
constexpr int TILE = 128 * SROW * 2;       // 34816 B
constexpr int QH_OFF = 0, QL_OFF = TILE, KH_OFF = 2*TILE, KL_OFF = 3*TILE, V_OFF = 4*TILE;
constexpr int SMEM_SZ = 5 * TILE;          // 174080
}

__global__ __launch_bounds__(256, 1) void flash_attn_kernel(
    const __nv_bfloat16* __restrict__ Qhi, const __nv_bfloat16* __restrict__ Qlo,
    const __nv_bfloat16* __restrict__ Khi, const __nv_bfloat16* __restrict__ Klo,
    const __half* __restrict__ Vt, __half* __restrict__ Out)
{
    using namespace fa;
    extern __shared__ char smraw[];
    uint32_t sbase = smem_u32(smraw);

    int tid = threadIdx.x;
    int wid = tid >> 5, lane = tid & 31;
    int z = blockIdx.z, zb = z / NHc, zh = z % NHc;
    int rowBase = blockIdx.y * 128;
    int nb = rowBase / 128 + 1;

    const __nv_bfloat16* Qh = Qhi + (size_t)(zb * Sc) * Hc + zh * HDc;
    const __nv_bfloat16* Ql = Qlo + (size_t)(zb * Sc) * Hc + zh * HDc;
    const __nv_bfloat16* Kh = Khi + (size_t)(zb * Sc) * Hc + zh * HDc;
    const __nv_bfloat16* Kl = Klo + (size_t)(zb * Sc) * Hc + zh * HDc;
    const __half* V = Vt + (size_t)z * HDc * Sc;

    int lr = tid >> 4;
    int lc = (tid & 15) * 8;
    uint32_t lso = (uint32_t)(lr * SROW + lc) * 2;

    int mat = lane >> 3, r8 = lane & 7;
    int a_row = (mat & 1) * 8 + r8, a_k = (mat >> 1) * 8;
    int b_n   = (mat >> 1) * 8 + r8, b_k = (mat & 1) * 8;
    int gid = lane >> 2;
    int e2  = 2 * (lane & 3);

    float o[16][4];
    #pragma unroll
    for (int j = 0; j < 16; j++)
        #pragma unroll
        for (int c = 0; c < 4; c++) o[j][c] = 0.f;
    float m0 = -INFINITY, m1 = -INFINITY, l0 = 0.f, l1 = 0.f;

    #pragma unroll
    for (int it = 0; it < 8; it++) {
        int r = lr + it * 16;
        uint32_t so = lso + (uint32_t)(it * 16 * SROW) * 2;
        cp_async16(sbase + QH_OFF + so, Qh + (size_t)(rowBase + r) * Hc + lc);
        cp_async16(sbase + QL_OFF + so, Ql + (size_t)(rowBase + r) * Hc + lc);
    }

    for (int b = 0; b < nb; b++) {
        int sBase = b * 128;
        #pragma unroll
        for (int it = 0; it < 8; it++) {
            int r = lr + it * 16;
            uint32_t so = lso + (uint32_t)(it * 16 * SROW) * 2;
            cp_async16(sbase + KH_OFF + so, Kh + (size_t)(sBase + r) * Hc + lc);
            cp_async16(sbase + KL_OFF + so, Kl + (size_t)(sBase + r) * Hc + lc);
            cp_async16(sbase + V_OFF  + so, V + (size_t)r * Sc + sBase + lc);
        }
        CP_COMMIT();
        CP_WAIT(0);
        __syncthreads();

        float s[16][4];
        #pragma unroll
        for (int j = 0; j < 16; j++)
            #pragma unroll
            for (int c = 0; c < 4; c++) s[j][c] = 0.f;

        #pragma unroll
        for (int ks = 0; ks < 8; ks++) {
            uint32_t qoff = (uint32_t)((wid * 16 + a_row) * SROW + ks * 16 + a_k) * 2;
            uint32_t ah[4], al[4];
            ldsm_x4(ah, sbase + QH_OFF + qoff);
            ldsm_x4(al, sbase + QL_OFF + qoff);
            #pragma unroll
            for (int nt = 0; nt < 8; nt++) {
                uint32_t koff = (uint32_t)((nt * 16 + b_n) * SROW + ks * 16 + b_k) * 2;
                uint32_t bh[4], bl[4];
                ldsm_x4(bh, sbase + KH_OFF + koff);
                ldsm_x4(bl, sbase + KL_OFF + koff);
                #pragma unroll
                for (int h2 = 0; h2 < 2; h2++) {
                    mma_bf16(s[nt*2+h2], ah, bh[2*h2], bh[2*h2+1]);
                    mma_bf16(s[nt*2+h2], ah, bl[2*h2], bl[2*h2+1]);
                    mma_bf16(s[nt*2+h2], al, bh[2*h2], bh[2*h2+1]);
                }
            }
        }

        if (b == nb - 1) {
            int row0 = rowBase + wid * 16 + gid;
            #pragma unroll
            for (int j = 0; j < 16; j++) {
                int col = sBase + j * 8 + e2;
                if (col     > row0)     s[j][0] = -INFINITY;
                if (col + 1 > row0)     s[j][1] = -INFINITY;
                if (col     > row0 + 8) s[j][2] = -INFINITY;
                if (col + 1 > row0 + 8) s[j][3] = -INFINITY;
            }
        }

        float bm0 = -INFINITY, bm1 = -INFINITY;
        #pragma unroll
        for (int j = 0; j < 16; j++) {
            bm0 = fmaxf(bm0, fmaxf(s[j][0], s[j][1]));
            bm1 = fmaxf(bm1, fmaxf(s[j][2], s[j][3]));
        }
        #pragma unroll
        for (int off = 1; off <= 2; off <<= 1) {
            bm0 = fmaxf(bm0, __shfl_xor_sync(0xffffffffu, bm0, off));
            bm1 = fmaxf(bm1, __shfl_xor_sync(0xffffffffu, bm1, off));
        }
        float mn0 = fmaxf(m0, bm0), mn1 = fmaxf(m1, bm1);
        float cr0 = __expf(m0 - mn0), cr1 = __expf(m1 - mn1);
        m0 = mn0; m1 = mn1;

        float rs0 = 0.f, rs1 = 0.f;
        #pragma unroll
        for (int j = 0; j < 16; j++) {
            s[j][0] = __expf(s[j][0] - mn0);
            s[j][1] = __expf(s[j][1] - mn0);
            s[j][2] = __expf(s[j][2] - mn1);
            s[j][3] = __expf(s[j][3] - mn1);
            rs0 += s[j][0] + s[j][1];
            rs1 += s[j][2] + s[j][3];
        }
        #pragma unroll
        for (int off = 1; off <= 2; off <<= 1) {
            rs0 += __shfl_xor_sync(0xffffffffu, rs0, off);
            rs1 += __shfl_xor_sync(0xffffffffu, rs1, off);
        }
        l0 = l0 * cr0 + rs0;
        l1 = l1 * cr1 + rs1;
        #pragma unroll
        for (int j = 0; j < 16; j++) {
            o[j][0] *= cr0; o[j][1] *= cr0;
            o[j][2] *= cr1; o[j][3] *= cr1;
        }

        // PV: 2-pass (p hi + p lo), fp16 A-frags, V smem B
        #pragma unroll
        for (int kk = 0; kk < 8; kk++) {
            uint32_t ahp[4], alp[4];
            #pragma unroll
            for (int q = 0; q < 4; q++) {
                const float* sv = (q < 2) ? s[2*kk] : s[2*kk+1];
                float v0f = sv[(q & 1) * 2 + 0];
                float v1f = sv[(q & 1) * 2 + 1];
                __half h0, l0h, h1, l1h;
                split2h(v0f, h0, l0h);
                split2h(v1f, h1, l1h);
                __half2 hh = __half2(h0, h1), ll = __half2(l0h, l1h);
                ahp[q] = *(uint32_t*)&hh;
                alp[q] = *(uint32_t*)&ll;
            }
            #pragma unroll
            for (int nt = 0; nt < 8; nt++) {
                uint32_t voff = (uint32_t)((nt * 16 + b_n) * SROW + kk * 16 + b_k) * 2;
                uint32_t bv[4];
                ldsm_x4(bv, sbase + V_OFF + voff);
                #pragma unroll
                for (int h2i = 0; h2i < 2; h2i++) {
                    mma_f16(o[nt*2+h2i], ahp, bv[2*h2i], bv[2*h2i+1]);
                    mma_f16(o[nt*2+h2i], alp, bv[2*h2i], bv[2*h2i+1]);
                }
            }
        }
        __syncthreads();
    }

    float i0 = 1.f / l0, i1 = 1.f / l1;
    __half* ob = Out + (size_t)(zb * Sc + rowBase + wid * 16 + gid) * Hc + zh * HDc;
    #pragma unroll
    for (int j = 0; j < 16; j++) {
        int col = j * 8 + e2;
        *(__half2*)(ob + col) =
            __half2(__float2half_rn(o[j][0] * i0), __float2half_rn(o[j][1] * i0));
        *(__half2*)(ob + 8 * Hc + col) =
            __half2(__float2half_rn(o[j][2] * i1), __float2half_rn(o[j][3] * i1));
    }
}

// ==================================================================
// fp16 GEMM: C = (A [+A2]) @ B^T [+ADD]. BM=128, BN=128, BK=32,
// 256 thr, 8 warps 4x2 grid of 32x64 tiles, 3-stage cp.async.
// TWOA with runtime skipA2Col: blocks with colBase >= skipA2Col run
// single-pass (used for V columns of the qkv GEMM).
// ==================================================================
namespace hk {
constexpr int BM = 128, BN = 128, BK = 32, SROW = 40;
constexpr int PL = BM * SROW * 2;
}

template<bool ADDC, bool H16OUT, bool SILU, bool TWOA>
__global__ __launch_bounds__(256, 2) void h16_gemm_kernel(
    const __half* __restrict__ A, const __half* __restrict__ A2,
    const __half* __restrict__ B,
    float* __restrict__ Cf, __half* __restrict__ Ch,
    const float* __restrict__ ADDp,
    int K, int lda, int ldb, int ldc, int skipA2Col)
{
    using namespace hk;
    constexpr int BOFFB = TWOA ? 2 * PL : PL;
    constexpr int STAGE = BOFFB + PL;
    constexpr int NSTG  = 3;

    int rowBase = blockIdx.y * BM;
    int colBase = blockIdx.x * BN;
    bool useA2 = TWOA && (colBase < skipA2Col);

    extern __shared__ char smraw[];
    uint32_t sbase = smem_u32(smraw);

    int tid = threadIdx.x;
    int wid = tid >> 5, lane = tid & 31;
    int wm = wid & 3, wn = wid >> 2;

    int nch = K / BK;

    float acc[2][8][4];
    #pragma unroll
    for (int a = 0; a < 2; a++)
        #pragma unroll
        for (int b = 0; b < 8; b++)
            #pragma unroll
            for (int c = 0; c < 4; c++) acc[a][b][c] = 0.f;

    int ar = tid >> 2, sg = (tid & 3) * 8;
    uint32_t soff = (uint32_t)(ar * SROW + sg) * 2;

    auto issue = [&](int c) {
        int k0 = c * BK;
        uint32_t st = sbase + (c % NSTG) * STAGE;
        #pragma unroll
        for (int it = 0; it < 2; it++) {
            int r = ar + it * 64;
            uint32_t o = soff + (uint32_t)(it * 64 * SROW) * 2;
            cp_async16(st + o,         A + (size_t)(rowBase + r) * lda + k0 + sg);
            if (TWOA && useA2)
                cp_async16(st + PL + o, A2 + (size_t)(rowBase + r) * lda + k0 + sg);
            cp_async16(st + BOFFB + o, B + (size_t)(colBase + r) * ldb + k0 + sg);
        }
    };

    int mat = lane >> 3, r8 = lane & 7;
    int a_row = (mat & 1) * 8 + r8, a_k = (mat >> 1) * 8;
    int b_n   = (mat >> 1) * 8 + r8, b_k = (mat & 1) * 8;

    issue(0); CP_COMMIT();
    if (nch > 1) { issue(1); CP_COMMIT(); } else { CP_COMMIT(); }

    for (int c = 0; c < nch; ++c) {
        if (c + 2 < nch) issue(c + 2);
        CP_COMMIT();
        CP_WAIT(2);
        __syncthreads();

        uint32_t st = sbase + (c % NSTG) * STAGE;
        #pragma unroll
        for (int ks = 0; ks < 2; ++ks) {
            uint32_t af[2][4], af2[2][4];
            #pragma unroll
            for (int mt = 0; mt < 2; ++mt) {
                uint32_t off = (uint32_t)((wm * 32 + mt * 16 + a_row) * SROW
                                          + ks * 16 + a_k) * 2;
                ldsm_x4(af[mt], st + off);
                if (TWOA && useA2) ldsm_x4(af2[mt], st + PL + off);
            }
            #pragma unroll
            for (int nt = 0; nt < 4; ++nt) {
                uint32_t boff = (uint32_t)((wn * 64 + nt * 16 + b_n) * SROW
                                           + ks * 16 + b_k) * 2;
                uint32_t bf[4];
                ldsm_x4(bf, st + BOFFB + boff);
                #pragma unroll
                for (int mt = 0; mt < 2; ++mt) {
                    #pragma unroll
                    for (int h2 = 0; h2 < 2; ++h2) {
                        mma_f16(acc[mt][nt*2+h2], af[mt], bf[2*h2], bf[2*h2+1]);
                        if (TWOA && useA2)
                            mma_f16(acc[mt][nt*2+h2], af2[mt], bf[2*h2], bf[2*h2+1]);
                    }
                }
            }
        }
        __syncthreads();
    }

    #pragma unroll
    for (int mt = 0; mt < 2; ++mt) {
        int r = rowBase + wm * 32 + mt * 16 + (lane >> 2);
        #pragma unroll
        for (int j8 = 0; j8 < 8; ++j8) {
            int cc = colBase + wn * 64 + j8 * 8 + 2 * (lane & 3);
            float v0 = acc[mt][j8][0], v1 = acc[mt][j8][1];
            float v2 = acc[mt][j8][2], v3 = acc[mt][j8][3];
            if (SILU) {
                float a0 = v0 / (1.f + __expf(-v0)) * v1;
                float a1 = v2 / (1.f + __expf(-v2)) * v3;
                Ch[(size_t)r * ldc + (cc >> 1)]       = __float2half_rn(a0);
                Ch[(size_t)(r + 8) * ldc + (cc >> 1)] = __float2half_rn(a1);
            } else if (H16OUT) {
                *(__half2*)(Ch + (size_t)r * ldc + cc) =
                    __half2(__float2half_rn(v0), __float2half_rn(v1));
                *(__half2*)(Ch + (size_t)(r + 8) * ldc + cc) =
                    __half2(__float2half_rn(v2), __float2half_rn(v3));
            } else {
                if (ADDC) {
                    float2 a0 = *(const float2*)(ADDp + (size_t)r * ldc + cc);
                    float2 a1 = *(const float2*)(ADDp + (size_t)(r + 8) * ldc + cc);
                    v0 += a0.x; v1 += a0.y; v2 += a1.x; v3 += a1.y;
                }
                *(float2*)(Cf + (size_t)r * ldc + cc)       = make_float2(v0, v1);
                *(float2*)(Cf + (size_t)(r + 8) * ldc + cc) = make_float2(v2, v3);
            }
        }
    }
}

// ---------------- host launcher ----------------
extern "C" void kernel_launch(void* const* d_in, const int* in_sizes, int n_in,
                              void* d_out, int out_size)
{
    const float* hs    = (const float*)d_in[0];
    const float* resid = (const float*)d_in[1];
    const float* cosp  = (const float*)d_in[2];
    const float* sinp  = (const float*)d_in[3];
    const float* w_qkv = (const float*)d_in[4];
    const float* w_o   = (const float*)d_in[5];
    const float* w_gu  = (const float*)d_in[6];
    const float* w_dn  = (const float*)d_in[7];
    const float* ln1   = (const float*)d_in[8];
    const float* ln2   = (const float*)d_in[9];

    float* out     = (float*)d_out;
    float* mlp_out = out;
    float* res2    = out + (size_t)Tc * Hc;

    float *p_res1, *p_qkv;
    cudaGetSymbolAddress((void**)&p_res1, g_res1);
    cudaGetSymbolAddress((void**)&p_qkv,  g_qkv);
    __nv_bfloat16 *qh,*ql,*kh,*kl;
    cudaGetSymbolAddress((void**)&qh, g_q_hi); cudaGetSymbolAddress((void**)&ql, g_q_lo);
    cudaGetSymbolAddress((void**)&kh, g_k_hi); cudaGetSymbolAddress((void**)&kl, g_k_lo);
    __half *nh1,*nh2,*wqh,*vth,*ath,*n2h,*ach,*woh,*wgh,*wdh;
    cudaGetSymbolAddress((void**)&nh1, g_n_h1);
    cudaGetSymbolAddress((void**)&nh2, g_n_h2);
    cudaGetSymbolAddress((void**)&wqh, g_wqkv_h);
    cudaGetSymbolAddress((void**)&vth, g_vt_h);
    cudaGetSymbolAddress((void**)&ath, g_at_h);
    cudaGetSymbolAddress((void**)&n2h, g_n2_h);
    cudaGetSymbolAddress((void**)&ach, g_ac_h);
    cudaGetSymbolAddress((void**)&woh, g_wo_h);
    cudaGetSymbolAddress((void**)&wgh, g_wgu_h);
    cudaGetSymbolAddress((void**)&wdh, g_wdn_h);

    constexpr int SM1 = 3 * (2 * hk::PL);
    constexpr int SM2 = 3 * (3 * hk::PL);
    cudaFuncSetAttribute(flash_attn_kernel, cudaFuncAttributeMaxDynamicSharedMemorySize, fa::SMEM_SZ);
    cudaFuncSetAttribute(h16_gemm_kernel<true, false,false,false>, cudaFuncAttributeMaxDynamicSharedMemorySize, SM1);
    cudaFuncSetAttribute(h16_gemm_kernel<false,false,false,false>, cudaFuncAttributeMaxDynamicSharedMemorySize, SM1);
    cudaFuncSetAttribute(h16_gemm_kernel<false,false,true, false>, cudaFuncAttributeMaxDynamicSharedMemorySize, SM1);
    cudaFuncSetAttribute(h16_gemm_kernel<false,false,false,true >, cudaFuncAttributeMaxDynamicSharedMemorySize, SM2);

    // weight prep
    transpose_h16_kernel<<<dim3(3*Hc/32, Hc/32), 256>>>(w_qkv, 0, 0, 3*Hc, wqh, 0, Hc, 0);
    transpose_h16_kernel<<<dim3(Hc/32,   Hc/32), 256>>>(w_o,  0, 0, Hc,   woh, 0, Hc, 0);
    transpose_h16_kernel<<<dim3(2*Ic/32, Hc/32), 256>>>(w_gu, 0, 0, 2*Ic, wgh, 0, Hc, Ic);
    transpose_h16_kernel<<<dim3(Hc/32,   Ic/32), 256>>>(w_dn, 0, 0, Hc,   wdh, 0, Ic, 0);

    // 1) res1 + RMSNorm -> fp16 hi/lo duo
    add_rmsnorm_kernel<<<Tc, 256>>>(hs, resid, ln1, p_res1, nh1, nh2, nullptr);

    // 2) qkv = normed @ w_qkv (fp16 TWOA; V columns single-pass)
    h16_gemm_kernel<false,false,false,true><<<dim3(3*Hc/128, Tc/128), 256, SM2>>>(
        nh1, nh2, wqh, p_qkv, nullptr, nullptr, Hc, Hc, Hc, 3*Hc, 2*Hc);

    // 3) RoPE (scale folded into Q) + V transpose (fp16)
    rope_kernel<<<(Tc*2*NHc*HALFc)/256, 256>>>(p_qkv, cosp, sinp, qh, ql, kh, kl);
    transpose_h16_kernel<<<dim3(HDc/32, Sc/32, Bc*NHc), 256>>>(
        p_qkv + 2*Hc, (long long)Sc*3*Hc, HDc, 3*Hc, vth, (long long)HDc*Sc, Sc, 0);

    // 4) fused flash attention -> ath fp16
    flash_attn_kernel<<<dim3(1, Sc/128, Bc*NHc), 256, fa::SMEM_SZ>>>(
        qh, ql, kh, kl, vth, ath);

    // 5) res2 = attn @ w_o + res1 (fp16 1-pass, into output)
    h16_gemm_kernel<true,false,false,false><<<dim3(Hc/128, Tc/128), 256, SM1>>>(
        ath, nullptr, woh, res2, nullptr, p_res1, Hc, Hc, Hc, Hc, 1 << 30);

    // 6) RMSNorm(res2) -> fp16 single plane
    add_rmsnorm_kernel<<<Tc, 256>>>(res2, nullptr, ln2, nullptr, nullptr, nullptr, n2h);

    // 7) ac = silu(gate)*up fused (fp16 1-pass, interleaved weights)
    h16_gemm_kernel<false,false,true,false><<<dim3(2*Ic/128, Tc/128), 256, SM1>>>(
        n2h, nullptr, wgh, nullptr, ach, nullptr, Hc, Hc, Hc, Ic, 1 << 30);

    // 8) mlp_out = ac @ w_down (fp16 1-pass, into output)
    h16_gemm_kernel<false,false,false,false><<<dim3(Hc/128, Tc/128), 256, SM1>>>(
        ach, nullptr, wdh, mlp_out, nullptr, nullptr, Ic, Ic, Ic, Hc, 1 << 30);
}

// round 17
// speedup vs baseline: 1.0180x; 1.0180x over previous
#include <cuda_runtime.h>
#include <cuda_bf16.h>
#include <cuda_fp16.h>
#include <math.h>
#include <stdint.h>

namespace {
constexpr int Bc  = 2;
constexpr int Sc  = 2048;
constexpr int Hc  = 4096;
constexpr int NHc = 32;
constexpr int HDc = 128;
constexpr int Ic  = 11008;
constexpr int Tc  = Bc * Sc;
constexpr int HALFc = HDc / 2;
constexpr float EPSc = 1e-6f;
constexpr float SCALEc = 0.08838834764831843f;
}

// ---------------- device scratch ----------------
__device__ float g_res1[(size_t)Tc * Hc];
__device__ float g_qkv [(size_t)Tc * 3 * Hc];

__device__ __nv_bfloat16 g_q_hi[(size_t)Tc * Hc], g_q_lo[(size_t)Tc * Hc];
__device__ __nv_bfloat16 g_k_hi[(size_t)Tc * Hc], g_k_lo[(size_t)Tc * Hc];

__device__ __half g_n_h1 [(size_t)Tc * Hc], g_n_h2 [(size_t)Tc * Hc];
__device__ __half g_wqkv_h[(size_t)3 * Hc * Hc];
__device__ __half g_vt_h [(size_t)Tc * Hc];
__device__ __half g_at_h [(size_t)Tc * Hc];
__device__ __half g_n2_h [(size_t)Tc * Hc];
__device__ __half g_ac_h [(size_t)Tc * Ic];
__device__ __half g_wo_h [(size_t)Hc * Hc];
__device__ __half g_wgu_h[(size_t)2 * Ic * Hc];
__device__ __half g_wdn_h[(size_t)Hc * Ic];

// ---------------- helpers ----------------
__device__ __forceinline__ uint32_t smem_u32(const void* p) {
    return (uint32_t)__cvta_generic_to_shared(p);
}
__device__ __forceinline__ void ldsm_x4(uint32_t (&r)[4], uint32_t addr) {
    asm volatile("ldmatrix.sync.aligned.m8n8.x4.shared.b16 {%0,%1,%2,%3}, [%4];"
                 : "=r"(r[0]), "=r"(r[1]), "=r"(r[2]), "=r"(r[3]) : "r"(addr));
}
__device__ __forceinline__ void mma_bf16(float (&d)[4], const uint32_t (&a)[4],
                                         uint32_t b0, uint32_t b1) {
    asm volatile("mma.sync.aligned.m16n8k16.row.col.f32.bf16.bf16.f32 "
        "{%0,%1,%2,%3}, {%4,%5,%6,%7}, {%8,%9}, {%0,%1,%2,%3};"
        : "+f"(d[0]), "+f"(d[1]), "+f"(d[2]), "+f"(d[3])
        : "r"(a[0]), "r"(a[1]), "r"(a[2]), "r"(a[3]), "r"(b0), "r"(b1));
}
__device__ __forceinline__ void mma_f16(float (&d)[4], const uint32_t (&a)[4],
                                        uint32_t b0, uint32_t b1) {
    asm volatile("mma.sync.aligned.m16n8k16.row.col.f32.f16.f16.f32 "
        "{%0,%1,%2,%3}, {%4,%5,%6,%7}, {%8,%9}, {%0,%1,%2,%3};"
        : "+f"(d[0]), "+f"(d[1]), "+f"(d[2]), "+f"(d[3])
        : "r"(a[0]), "r"(a[1]), "r"(a[2]), "r"(a[3]), "r"(b0), "r"(b1));
}
__device__ __forceinline__ void cp_async16(uint32_t dst, const void* src) {
    asm volatile("cp.async.cg.shared.global [%0], [%1], 16;" :: "r"(dst), "l"(src));
}
#define CP_COMMIT() asm volatile("cp.async.commit_group;" ::: "memory")
#define CP_WAIT(n)  asm volatile("cp.async.wait_group %0;" :: "n"(n) : "memory")
__device__ __forceinline__ void split2(float v, __nv_bfloat16& h, __nv_bfloat16& l) {
    h = __float2bfloat16(v);
    l = __float2bfloat16(v - __bfloat162float(h));
}
__device__ __forceinline__ void split2h(float v, __half& h, __half& l) {
    h = __float2half_rn(v);
    l = __float2half_rn(v - __half2float(h));
}

// ---------------- block reductions (256 thr) ----------------
__device__ __forceinline__ float block_reduce_sum_256(float v) {
    #pragma unroll
    for (int o = 16; o > 0; o >>= 1) v += __shfl_down_sync(0xffffffffu, v, o);
    __shared__ float red[8];
    int w = threadIdx.x >> 5, l = threadIdx.x & 31;
    if (l == 0) red[w] = v;
    __syncthreads();
    if (w == 0) {
        float x = (l < 8) ? red[l] : 0.f;
        #pragma unroll
        for (int o = 4; o > 0; o >>= 1) x += __shfl_down_sync(0xffu, x, o);
        if (l == 0) red[0] = x;
    }
    __syncthreads();
    float r = red[0];
    __syncthreads();
    return r;
}

// ------- add + RMSNorm -> fp16 hi/lo duo OR fp16 single plane -------
__global__ __launch_bounds__(256) void add_rmsnorm_kernel(
    const float* __restrict__ a, const float* __restrict__ b,
    const float* __restrict__ w, float* __restrict__ sum_out,
    __half* __restrict__ ohi, __half* __restrict__ olo,
    __half* __restrict__ osingle)
{
    int row = blockIdx.x;
    const float4* a4 = (const float4*)(a + (size_t)row * Hc);
    const float4* b4 = b ? (const float4*)(b + (size_t)row * Hc) : nullptr;
    const float4* w4 = (const float4*)w;
    float4* s4 = sum_out ? (float4*)(sum_out + (size_t)row * Hc) : nullptr;

    float4 v[4];
    float ss = 0.f;
    #pragma unroll
    for (int it = 0; it < 4; it++) {
        int idx = threadIdx.x + it * 256;
        float4 va = a4[idx];
        if (b4) { float4 vb = b4[idx]; va.x += vb.x; va.y += vb.y; va.z += vb.z; va.w += vb.w; }
        v[it] = va;
        ss += va.x * va.x + va.y * va.y + va.z * va.z + va.w * va.w;
    }
    float tot = block_reduce_sum_256(ss);
    float scale = rsqrtf(tot / (float)Hc + EPSc);
    #pragma unroll
    for (int it = 0; it < 4; it++) {
        int idx = threadIdx.x + it * 256;
        if (s4) s4[idx] = v[it];
        float4 vw = w4[idx];
        float y0 = v[it].x * scale * vw.x, y1 = v[it].y * scale * vw.y;
        float y2 = v[it].z * scale * vw.z, y3 = v[it].w * scale * vw.w;
        if (osingle) {
            __half2* o2 = (__half2*)(osingle + (size_t)row * Hc);
            o2[idx*2]   = __half2(__float2half_rn(y0), __float2half_rn(y1));
            o2[idx*2+1] = __half2(__float2half_rn(y2), __float2half_rn(y3));
        } else {
            __half2* oh2 = (__half2*)(ohi + (size_t)row * Hc);
            __half2* ol2 = (__half2*)(olo + (size_t)row * Hc);
            __half h0,l0,h1,l1,h2,l2,h3,l3;
            split2h(y0,h0,l0); split2h(y1,h1,l1); split2h(y2,h2,l2); split2h(y3,h3,l3);
            oh2[idx*2]   = __half2(h0,h1);
            oh2[idx*2+1] = __half2(h2,h3);
            ol2[idx*2]   = __half2(l0,l1);
            ol2[idx*2+1] = __half2(l2,l3);
        }
    }
}

// ------- RoPE: fp32 qkv -> Q/K bf16 hi/lo (SCALE folded into Q) -------
__global__ __launch_bounds__(256) void rope_kernel(
    const float* __restrict__ qkv, const float* __restrict__ cosp,
    const float* __restrict__ sinp,
    __nv_bfloat16* __restrict__ qhi, __nv_bfloat16* __restrict__ qlo,
    __nv_bfloat16* __restrict__ khi, __nv_bfloat16* __restrict__ klo)
{
    int idx = blockIdx.x * 256 + threadIdx.x;
    int d = idx & (HALFc - 1);
    int h = (idx >> 6) & (NHc - 1);
    int m = (idx >> 11) & 1;
    int t = idx >> 12;
    const float* p = qkv + (size_t)t * (3 * Hc) + m * Hc + h * HDc + d;
    float x1 = p[0], x2 = p[HALFc];
    float c = cosp[(size_t)t * HALFc + d];
    float s = sinp[(size_t)t * HALFc + d];
    float sc = m ? 1.f : SCALEc;
    float y1 = (x1 * c - x2 * s) * sc;
    float y2 = (x1 * s + x2 * c) * sc;
    __nv_bfloat16* dh = (m ? khi : qhi) + (size_t)t * Hc + h * HDc + d;
    __nv_bfloat16* dl = (m ? klo : qlo) + (size_t)t * Hc + h * HDc + d;
    __nv_bfloat16 h1, l1, h2, l2;
    split2(y1, h1, l1); split2(y2, h2, l2);
    dh[0] = h1; dh[HALFc] = h2;
    dl[0] = l1; dl[HALFc] = l2;
}

// ------- transpose fp32 [Y,X] -> fp16 [X,Y]; batched; optional interleave -------
__global__ __launch_bounds__(256) void transpose_h16_kernel(
    const float* __restrict__ in, long long inSb, long long inSh, int in_ld,
    __half* __restrict__ outp, long long outSz, int K, int interHalf)
{
    __shared__ float tile[32][33];
    int z = blockIdx.z, zb = z / NHc, zh = z % NHc;
    const float* inp = in + zb * inSb + zh * inSh;
    __half* op = outp + (long long)z * outSz;
    int tx = threadIdx.x & 31, ty = threadIdx.x >> 5;
    int gx = blockIdx.x * 32 + tx;
    #pragma unroll
    for (int i = 0; i < 4; i++) {
        int gy = blockIdx.y * 32 + ty + i * 8;
        tile[ty + i * 8][tx] = inp[(size_t)gy * in_ld + gx];
    }
    __syncthreads();
    int ox = blockIdx.y * 32 + tx;
    #pragma unroll
    for (int i = 0; i < 4; i++) {
        int oy = blockIdx.x * 32 + ty + i * 8;
        int oyr = interHalf ? ((oy < interHalf) ? 2 * oy : 2 * (oy - interHalf) + 1) : oy;
        op[(size_t)oyr * K + ox] = __float2half_rn(tile[tx][ty + i * 8]);
    }
}

// ==================================================================
// Fused flash attention, 64-col K/V sub-blocks, 2-stage pipeline.
// QK = bf16 3-pass, online softmax fp32, PV = fp16 1-pass.
// 8 warps x 16 rows. smem: Q(hi,lo 128x136) + 2 stages of
// {Khi,Klo 64x136 ; V^T 128x72}.
// ==================================================================
namespace fa {
constexpr int QROW = 136;                       // Q/K row stride (halves)
constexpr int VROW = 72;                        // V^T row stride (halves)
constexpr int QTILE = 128 * QROW * 2;           // 34816
constexpr int KSUB  = 64 * QROW * 2;            // 17408 per plane
constexpr int VSUB  = 128 * VROW * 2;           // 18432
constexpr int STG   = 2 * KSUB + VSUB;          // 53248
constexpr int ST0   = 2 * QTILE;                // 69632
constexpr int SMEM_SZ = ST0 + 2 * STG;          // 176128
}

__global__ __launch_bounds__(256, 1) void flash_attn_kernel(
    const __nv_bfloat16* __restrict__ Qhi, const __nv_bfloat16* __restrict__ Qlo,
    const __nv_bfloat16* __restrict__ Khi, const __nv_bfloat16* __restrict__ Klo,
    const __half* __restrict__ Vt, __half* __restrict__ Out)
{
    using namespace fa;
    extern __shared__ char smraw[];
    uint32_t sbase = smem_u32(smraw);

    int tid = threadIdx.x;
    int wid = tid >> 5, lane = tid & 31;
    int z = blockIdx.z, zb = z / NHc, zh = z % NHc;
    int rowBase = blockIdx.y * 128;
    int nsb = rowBase / 64 + 2;                 // 64-col sub-blocks

    const __nv_bfloat16* Qh = Qhi + (size_t)(zb * Sc) * Hc + zh * HDc;
    const __nv_bfloat16* Ql = Qlo + (size_t)(zb * Sc) * Hc + zh * HDc;
    const __nv_bfloat16* Kh = Khi + (size_t)(zb * Sc) * Hc + zh * HDc;
    const __nv_bfloat16* Kl = Klo + (size_t)(zb * Sc) * Hc + zh * HDc;
    const __half* V = Vt + (size_t)z * HDc * Sc;

    // loaders
    int qlr = tid >> 4, qlc = (tid & 15) * 8;                 // Q/K: 16 rows/pass
    uint32_t qso = (uint32_t)(qlr * QROW + qlc) * 2;
    int vlr = tid >> 3, vlc = (tid & 7) * 8;                  // V: 32 rows/pass
    uint32_t vso = (uint32_t)(vlr * VROW + vlc) * 2;

    auto issue_sub = [&](int sb) {
        int sBase = sb * 64;
        uint32_t st = sbase + ST0 + (sb & 1) * STG;
        #pragma unroll
        for (int it = 0; it < 4; it++) {                      // K: 64 rows
            int r = qlr + it * 16;
            uint32_t so = qso + (uint32_t)(it * 16 * QROW) * 2;
            cp_async16(st + so,        Kh + (size_t)(sBase + r) * Hc + qlc);
            cp_async16(st + KSUB + so, Kl + (size_t)(sBase + r) * Hc + qlc);
        }
        #pragma unroll
        for (int it = 0; it < 4; it++) {                      // V^T: 128 rows x 64
            int r = vlr + it * 32;
            uint32_t so = vso + (uint32_t)(it * 32 * VROW) * 2;
            cp_async16(st + 2 * KSUB + so, V + (size_t)r * Sc + sBase + vlc);
        }
    };

    // ldmatrix lane addressing
    int mat = lane >> 3, r8 = lane & 7;
    int a_row = (mat & 1) * 8 + r8, a_k = (mat >> 1) * 8;
    int b_n   = (mat >> 1) * 8 + r8, b_k = (mat & 1) * 8;
    int gid = lane >> 2;
    int e2  = 2 * (lane & 3);

    float o[16][4];
    #pragma unroll
    for (int j = 0; j < 16; j++)
        #pragma unroll
        for (int c = 0; c < 4; c++) o[j][c] = 0.f;
    float m0 = -INFINITY, m1 = -INFINITY, l0 = 0.f, l1 = 0.f;

    // load Q + sub-block 0, one group
    #pragma unroll
    for (int it = 0; it < 8; it++) {
        int r = qlr + it * 16;
        uint32_t so = qso + (uint32_t)(it * 16 * QROW) * 2;
        cp_async16(sbase + so,         Qh + (size_t)(rowBase + r) * Hc + qlc);
        cp_async16(sbase + QTILE + so, Ql + (size_t)(rowBase + r) * Hc + qlc);
    }
    issue_sub(0);
    CP_COMMIT();

    for (int sb = 0; sb < nsb; sb++) {
        if (sb + 1 < nsb) { issue_sub(sb + 1); CP_COMMIT(); CP_WAIT(1); }
        else              { CP_WAIT(0); }
        __syncthreads();

        int sBase = sb * 64;
        uint32_t st = sbase + ST0 + (sb & 1) * STG;

        // S = Q @ K^T (bf16 3-pass), 64 cols
        float s[8][4];
        #pragma unroll
        for (int j = 0; j < 8; j++)
            #pragma unroll
            for (int c = 0; c < 4; c++) s[j][c] = 0.f;

        #pragma unroll
        for (int ks = 0; ks < 8; ks++) {
            uint32_t qoff = (uint32_t)((wid * 16 + a_row) * QROW + ks * 16 + a_k) * 2;
            uint32_t ah[4], al[4];
            ldsm_x4(ah, sbase + qoff);
            ldsm_x4(al, sbase + QTILE + qoff);
            #pragma unroll
            for (int nt = 0; nt < 4; nt++) {
                uint32_t koff = (uint32_t)((nt * 16 + b_n) * QROW + ks * 16 + b_k) * 2;
                uint32_t bh[4], bl[4];
                ldsm_x4(bh, st + koff);
                ldsm_x4(bl, st + KSUB + koff);
                #pragma unroll
                for (int h2 = 0; h2 < 2; h2++) {
                    mma_bf16(s[nt*2+h2], ah, bh[2*h2], bh[2*h2+1]);
                    mma_bf16(s[nt*2+h2], ah, bl[2*h2], bl[2*h2+1]);
                    mma_bf16(s[nt*2+h2], al, bh[2*h2], bh[2*h2+1]);
                }
            }
        }

        // causal mask (only sub-blocks overlapping diagonal)
        if (sBase + 63 > rowBase) {
            int row0 = rowBase + wid * 16 + gid;
            #pragma unroll
            for (int j = 0; j < 8; j++) {
                int col = sBase + j * 8 + e2;
                if (col     > row0)     s[j][0] = -INFINITY;
                if (col + 1 > row0)     s[j][1] = -INFINITY;
                if (col     > row0 + 8) s[j][2] = -INFINITY;
                if (col + 1 > row0 + 8) s[j][3] = -INFINITY;
            }
        }

        // online softmax update
        float bm0 = -INFINITY, bm1 = -INFINITY;
        #pragma unroll
        for (int j = 0; j < 8; j++) {
            bm0 = fmaxf(bm0, fmaxf(s[j][0], s[j][1]));
            bm1 = fmaxf(bm1, fmaxf(s[j][2], s[j][3]));
        }
        #pragma unroll
        for (int off = 1; off <= 2; off <<= 1) {
            bm0 = fmaxf(bm0, __shfl_xor_sync(0xffffffffu, bm0, off));
            bm1 = fmaxf(bm1, __shfl_xor_sync(0xffffffffu, bm1, off));
        }
        float mn0 = fmaxf(m0, bm0), mn1 = fmaxf(m1, bm1);
        float cr0 = __expf(m0 - mn0), cr1 = __expf(m1 - mn1);
        m0 = mn0; m1 = mn1;

        float rs0 = 0.f, rs1 = 0.f;
        #pragma unroll
        for (int j = 0; j < 8; j++) {
            s[j][0] = __expf(s[j][0] - mn0);
            s[j][1] = __expf(s[j][1] - mn0);
            s[j][2] = __expf(s[j][2] - mn1);
            s[j][3] = __expf(s[j][3] - mn1);
            rs0 += s[j][0] + s[j][1];
            rs1 += s[j][2] + s[j][3];
        }
        #pragma unroll
        for (int off = 1; off <= 2; off <<= 1) {
            rs0 += __shfl_xor_sync(0xffffffffu, rs0, off);
            rs1 += __shfl_xor_sync(0xffffffffu, rs1, off);
        }
        l0 = l0 * cr0 + rs0;
        l1 = l1 * cr1 + rs1;
        #pragma unroll
        for (int j = 0; j < 16; j++) {
            o[j][0] *= cr0; o[j][1] *= cr0;
            o[j][2] *= cr1; o[j][3] *= cr1;
        }

        // PV: fp16 1-pass; A frags from p, B = V^T sub-tile
        #pragma unroll
        for (int kk = 0; kk < 4; kk++) {
            __half2 h0 = __half2(__float2half_rn(s[2*kk][0]),   __float2half_rn(s[2*kk][1]));
            __half2 h1 = __half2(__float2half_rn(s[2*kk][2]),   __float2half_rn(s[2*kk][3]));
            __half2 h2 = __half2(__float2half_rn(s[2*kk+1][0]), __float2half_rn(s[2*kk+1][1]));
            __half2 h3 = __half2(__float2half_rn(s[2*kk+1][2]), __float2half_rn(s[2*kk+1][3]));
            uint32_t a[4];
            a[0] = *(uint32_t*)&h0;
            a[1] = *(uint32_t*)&h1;
            a[2] = *(uint32_t*)&h2;
            a[3] = *(uint32_t*)&h3;
            #pragma unroll
            for (int nt = 0; nt < 8; nt++) {
                uint32_t voff = (uint32_t)((nt * 16 + b_n) * VROW + kk * 16 + b_k) * 2;
                uint32_t bv[4];
                ldsm_x4(bv, st + 2 * KSUB + voff);
                #pragma unroll
                for (int h2i = 0; h2i < 2; h2i++)
                    mma_f16(o[nt*2+h2i], a, bv[2*h2i], bv[2*h2i+1]);
            }
        }
        __syncthreads();
    }

    float i0 = 1.f / l0, i1 = 1.f / l1;
    __half* ob = Out + (size_t)(zb * Sc + rowBase + wid * 16 + gid) * Hc + zh * HDc;
    #pragma unroll
    for (int j = 0; j < 16; j++) {
        int col = j * 8 + e2;
        *(__half2*)(ob + col) =
            __half2(__float2half_rn(o[j][0] * i0), __float2half_rn(o[j][1] * i0));
        *(__half2*)(ob + 8 * Hc + col) =
            __half2(__float2half_rn(o[j][2] * i1), __float2half_rn(o[j][3] * i1));
    }
}

// ==================================================================
// fp16 GEMM: C = (A [+A2]) @ B^T [+ADD]. BM=128, BN=128, BK=32,
// 256 thr, 8 warps 4x2 grid of 32x64 tiles, 3-stage cp.async.
// ==================================================================
namespace hk {
constexpr int BM = 128, BN = 128, BK = 32, SROW = 40;
constexpr int PL = BM * SROW * 2;
}

template<bool ADDC, bool H16OUT, bool SILU, bool TWOA>
__global__ __launch_bounds__(256, 2) void h16_gemm_kernel(
    const __half* __restrict__ A, const __half* __restrict__ A2,
    const __half* __restrict__ B,
    float* __restrict__ Cf, __half* __restrict__ Ch,
    const float* __restrict__ ADDp,
    int K, int lda, int ldb, int ldc)
{
    using namespace hk;
    constexpr int BOFFB = TWOA ? 2 * PL : PL;
    constexpr int STAGE = BOFFB + PL;
    constexpr int NSTG  = 3;

    int rowBase = blockIdx.y * BM;
    int colBase = blockIdx.x * BN;

    extern __shared__ char smraw[];
    uint32_t sbase = smem_u32(smraw);

    int tid = threadIdx.x;
    int wid = tid >> 5, lane = tid & 31;
    int wm = wid & 3, wn = wid >> 2;

    int nch = K / BK;

    float acc[2][8][4];
    #pragma unroll
    for (int a = 0; a < 2; a++)
        #pragma unroll
        for (int b = 0; b < 8; b++)
            #pragma unroll
            for (int c = 0; c < 4; c++) acc[a][b][c] = 0.f;

    int ar = tid >> 2, sg = (tid & 3) * 8;
    uint32_t soff = (uint32_t)(ar * SROW + sg) * 2;

    auto issue = [&](int c) {
        int k0 = c * BK;
        uint32_t st = sbase + (c % NSTG) * STAGE;
        #pragma unroll
        for (int it = 0; it < 2; it++) {
            int r = ar + it * 64;
            uint32_t o = soff + (uint32_t)(it * 64 * SROW) * 2;
            cp_async16(st + o,         A + (size_t)(rowBase + r) * lda + k0 + sg);
            if (TWOA)
                cp_async16(st + PL + o, A2 + (size_t)(rowBase + r) * lda + k0 + sg);
            cp_async16(st + BOFFB + o, B + (size_t)(colBase + r) * ldb + k0 + sg);
        }
    };

    int mat = lane >> 3, r8 = lane & 7;
    int a_row = (mat & 1) * 8 + r8, a_k = (mat >> 1) * 8;
    int b_n   = (mat >> 1) * 8 + r8, b_k = (mat & 1) * 8;

    issue(0); CP_COMMIT();
    if (nch > 1) { issue(1); CP_COMMIT(); } else { CP_COMMIT(); }

    for (int c = 0; c < nch; ++c) {
        if (c + 2 < nch) issue(c + 2);
        CP_COMMIT();
        CP_WAIT(2);
        __syncthreads();

        uint32_t st = sbase + (c % NSTG) * STAGE;
        #pragma unroll
        for (int ks = 0; ks < 2; ++ks) {
            uint32_t af[2][4], af2[2][4];
            #pragma unroll
            for (int mt = 0; mt < 2; ++mt) {
                uint32_t off = (uint32_t)((wm * 32 + mt * 16 + a_row) * SROW
                                          + ks * 16 + a_k) * 2;
                ldsm_x4(af[mt], st + off);
                if (TWOA) ldsm_x4(af2[mt], st + PL + off);
            }
            #pragma unroll
            for (int nt = 0; nt < 4; ++nt) {
                uint32_t boff = (uint32_t)((wn * 64 + nt * 16 + b_n) * SROW
                                           + ks * 16 + b_k) * 2;
                uint32_t bf[4];
                ldsm_x4(bf, st + BOFFB + boff);
                #pragma unroll
                for (int mt = 0; mt < 2; ++mt) {
                    #pragma unroll
                    for (int h2 = 0; h2 < 2; ++h2) {
                        mma_f16(acc[mt][nt*2+h2], af[mt], bf[2*h2], bf[2*h2+1]);
                        if (TWOA)
                            mma_f16(acc[mt][nt*2+h2], af2[mt], bf[2*h2], bf[2*h2+1]);
                    }
                }
            }
        }
        __syncthreads();
    }

    #pragma unroll
    for (int mt = 0; mt < 2; ++mt) {
        int r = rowBase + wm * 32 + mt * 16 + (lane >> 2);
        #pragma unroll
        for (int j8 = 0; j8 < 8; ++j8) {
            int cc = colBase + wn * 64 + j8 * 8 + 2 * (lane & 3);
            float v0 = acc[mt][j8][0], v1 = acc[mt][j8][1];
            float v2 = acc[mt][j8][2], v3 = acc[mt][j8][3];
            if (SILU) {
                float a0 = v0 / (1.f + __expf(-v0)) * v1;
                float a1 = v2 / (1.f + __expf(-v2)) * v3;
                Ch[(size_t)r * ldc + (cc >> 1)]       = __float2half_rn(a0);
                Ch[(size_t)(r + 8) * ldc + (cc >> 1)] = __float2half_rn(a1);
            } else if (H16OUT) {
                *(__half2*)(Ch + (size_t)r * ldc + cc) =
                    __half2(__float2half_rn(v0), __float2half_rn(v1));
                *(__half2*)(Ch + (size_t)(r + 8) * ldc + cc) =
                    __half2(__float2half_rn(v2), __float2half_rn(v3));
            } else {
                if (ADDC) {
                    float2 a0 = *(const float2*)(ADDp + (size_t)r * ldc + cc);
                    float2 a1 = *(const float2*)(ADDp + (size_t)(r + 8) * ldc + cc);
                    v0 += a0.x; v1 += a0.y; v2 += a1.x; v3 += a1.y;
                }
                *(float2*)(Cf + (size_t)r * ldc + cc)       = make_float2(v0, v1);
                *(float2*)(Cf + (size_t)(r + 8) * ldc + cc) = make_float2(v2, v3);
            }
        }
    }
}

// ---------------- host launcher ----------------
extern "C" void kernel_launch(void* const* d_in, const int* in_sizes, int n_in,
                              void* d_out, int out_size)
{
    const float* hs    = (const float*)d_in[0];
    const float* resid = (const float*)d_in[1];
    const float* cosp  = (const float*)d_in[2];
    const float* sinp  = (const float*)d_in[3];
    const float* w_qkv = (const float*)d_in[4];
    const float* w_o   = (const float*)d_in[5];
    const float* w_gu  = (const float*)d_in[6];
    const float* w_dn  = (const float*)d_in[7];
    const float* ln1   = (const float*)d_in[8];
    const float* ln2   = (const float*)d_in[9];

    float* out     = (float*)d_out;
    float* mlp_out = out;
    float* res2    = out + (size_t)Tc * Hc;

    float *p_res1, *p_qkv;
    cudaGetSymbolAddress((void**)&p_res1, g_res1);
    cudaGetSymbolAddress((void**)&p_qkv,  g_qkv);
    __nv_bfloat16 *qh,*ql,*kh,*kl;
    cudaGetSymbolAddress((void**)&qh, g_q_hi); cudaGetSymbolAddress((void**)&ql, g_q_lo);
    cudaGetSymbolAddress((void**)&kh, g_k_hi); cudaGetSymbolAddress((void**)&kl, g_k_lo);
    __half *nh1,*nh2,*wqh,*vth,*ath,*n2h,*ach,*woh,*wgh,*wdh;
    cudaGetSymbolAddress((void**)&nh1, g_n_h1);
    cudaGetSymbolAddress((void**)&nh2, g_n_h2);
    cudaGetSymbolAddress((void**)&wqh, g_wqkv_h);
    cudaGetSymbolAddress((void**)&vth, g_vt_h);
    cudaGetSymbolAddress((void**)&ath, g_at_h);
    cudaGetSymbolAddress((void**)&n2h, g_n2_h);
    cudaGetSymbolAddress((void**)&ach, g_ac_h);
    cudaGetSymbolAddress((void**)&woh, g_wo_h);
    cudaGetSymbolAddress((void**)&wgh, g_wgu_h);
    cudaGetSymbolAddress((void**)&wdh, g_wdn_h);

    constexpr int SM1 = 3 * (2 * hk::PL);
    constexpr int SM2 = 3 * (3 * hk::PL);
    cudaFuncSetAttribute(flash_attn_kernel, cudaFuncAttributeMaxDynamicSharedMemorySize, fa::SMEM_SZ);
    cudaFuncSetAttribute(h16_gemm_kernel<true, false,false,false>, cudaFuncAttributeMaxDynamicSharedMemorySize, SM1);
    cudaFuncSetAttribute(h16_gemm_kernel<false,false,false,false>, cudaFuncAttributeMaxDynamicSharedMemorySize, SM1);
    cudaFuncSetAttribute(h16_gemm_kernel<false,false,true, false>, cudaFuncAttributeMaxDynamicSharedMemorySize, SM1);
    cudaFuncSetAttribute(h16_gemm_kernel<false,false,false,true >, cudaFuncAttributeMaxDynamicSharedMemorySize, SM2);

    // weight prep
    transpose_h16_kernel<<<dim3(3*Hc/32, Hc/32), 256>>>(w_qkv, 0, 0, 3*Hc, wqh, 0, Hc, 0);
    transpose_h16_kernel<<<dim3(Hc/32,   Hc/32), 256>>>(w_o,  0, 0, Hc,   woh, 0, Hc, 0);
    transpose_h16_kernel<<<dim3(2*Ic/32, Hc/32), 256>>>(w_gu, 0, 0, 2*Ic, wgh, 0, Hc, Ic);
    transpose_h16_kernel<<<dim3(Hc/32,   Ic/32), 256>>>(w_dn, 0, 0, Hc,   wdh, 0, Ic, 0);

    // 1) res1 + RMSNorm -> fp16 hi/lo duo
    add_rmsnorm_kernel<<<Tc, 256>>>(hs, resid, ln1, p_res1, nh1, nh2, nullptr);

    // 2) qkv = normed @ w_qkv (fp16 2-pass TWOA, fp32 out)
    h16_gemm_kernel<false,false,false,true><<<dim3(3*Hc/128, Tc/128), 256, SM2>>>(
        nh1, nh2, wqh, p_qkv, nullptr, nullptr, Hc, Hc, Hc, 3*Hc);

    // 3) RoPE (scale folded into Q) + V transpose (fp16)
    rope_kernel<<<(Tc*2*NHc*HALFc)/256, 256>>>(p_qkv, cosp, sinp, qh, ql, kh, kl);
    transpose_h16_kernel<<<dim3(HDc/32, Sc/32, Bc*NHc), 256>>>(
        p_qkv + 2*Hc, (long long)Sc*3*Hc, HDc, 3*Hc, vth, (long long)HDc*Sc, Sc, 0);

    // 4) fused flash attention (pipelined) -> ath fp16
    flash_attn_kernel<<<dim3(1, Sc/128, Bc*NHc), 256, fa::SMEM_SZ>>>(
        qh, ql, kh, kl, vth, ath);

    // 5) res2 = attn @ w_o + res1 (fp16 1-pass, into output)
    h16_gemm_kernel<true,false,false,false><<<dim3(Hc/128, Tc/128), 256, SM1>>>(
        ath, nullptr, woh, res2, nullptr, p_res1, Hc, Hc, Hc, Hc);

    // 6) RMSNorm(res2) -> fp16 single plane
    add_rmsnorm_kernel<<<Tc, 256>>>(res2, nullptr, ln2, nullptr, nullptr, nullptr, n2h);

    // 7) ac = silu(gate)*up fused (fp16 1-pass, interleaved weights)
    h16_gemm_kernel<false,false,true,false><<<dim3(2*Ic/128, Tc/128), 256, SM1>>>(
        n2h, nullptr, wgh, nullptr, ach, nullptr, Hc, Hc, Hc, Ic);

    // 8) mlp_out = ac @ w_down (fp16 1-pass, into output)
    h16_gemm_kernel<false,false,false,false><<<dim3(Hc/128, Tc/128), 256, SM1>>>(
        ach, nullptr, wdh, mlp_out, nullptr, nullptr, Ic, Ic, Ic, Hc);
}